// round 1
// baseline (speedup 1.0000x reference)
#include <cuda_runtime.h>

#define S_TOKENS 16384
#define D_MODEL  4096
#define N_EXP    64
#define TM       128              // tokens per CTA
#define KB       16               // k-chunk
#define NC       (D_MODEL / KB)   // 256 chunks
#define XS_STR   (TM + 2)         // 130: (2k+t)%32 conflict-free STS, 8B-aligned rows
#define WS_STR   (N_EXP + 4)      // 68: 16B-aligned rows for float4 LDS
#define LS_STR   (N_EXP + 1)      // 65: (t+e)%32 conflict-free row scans

__device__ float g_imp[N_EXP];
__device__ int   g_cnt[N_EXP];

__global__ void zero_kernel() {
    int t = threadIdx.x;
    if (t < N_EXP) { g_imp[t] = 0.0f; g_cnt[t] = 0; }
}

__device__ __forceinline__ unsigned long long pack2(float v) {
    unsigned long long r;
    asm("mov.b64 %0, {%1, %1};" : "=l"(r) : "r"(__float_as_uint(v)));
    return r;
}
__device__ __forceinline__ void ffma2(unsigned long long& c,
                                      unsigned long long a,
                                      unsigned long long b) {
    // packed fp32x2 FMA: c.lo += a.lo*b.lo ; c.hi += a.hi*b.hi
    asm("fma.rn.f32x2 %0, %1, %2, %0;" : "+l"(c) : "l"(a), "l"(b));
}

struct SmemGemm {
    float Xs[2][KB][XS_STR];   // [buf][k][token]
    float Ws[2][KB][WS_STR];   // [buf][k][expert]
};
struct SmemEpi {
    float L[TM][LS_STR];       // logits [token][expert]
    float tmax[TM];
    float trcp[TM];
    int   hist[N_EXP];
};

__global__ __launch_bounds__(256, 1)
void gate_kernel(const float* __restrict__ x,
                 const float* __restrict__ wg,
                 float* __restrict__ out)
{
    __shared__ union { SmemGemm g; SmemEpi e; } sm;

    const int tid     = threadIdx.x;
    const int tokBase = blockIdx.x * TM;

    // compute mapping: 16x16 thread grid
    const int tx = tid & 15;   // expert group: experts tx*4 .. tx*4+3
    const int ty = tid >> 4;   // token group: tokens ty*8 .. ty*8+7 (4 pairs)

    // loader mapping
    const int lk = tid & 15;   // k within chunk
    const int lr = tid >> 4;   // 0..15

    const float* xbase = x + (size_t)tokBase * D_MODEL;

    float xr[8], wr[4];

    // prefetch chunk 0
#pragma unroll
    for (int p = 0; p < 8; p++)
        xr[p] = xbase[(size_t)(lr + 16 * p) * D_MODEL + lk];
#pragma unroll
    for (int p = 0; p < 4; p++)
        wr[p] = wg[(size_t)(lr + 16 * p) * D_MODEL + lk];
#pragma unroll
    for (int p = 0; p < 8; p++) sm.g.Xs[0][lk][lr + 16 * p] = xr[p];
#pragma unroll
    for (int p = 0; p < 4; p++) sm.g.Ws[0][lk][lr + 16 * p] = wr[p];
    __syncthreads();

    unsigned long long acc[4][4];
#pragma unroll
    for (int i = 0; i < 4; i++)
#pragma unroll
        for (int j = 0; j < 4; j++) acc[i][j] = 0ull;   // bits of (0.f,0.f)

    for (int c = 0; c < NC; c++) {
        const int b = c & 1;

        if (c + 1 < NC) {
            const int k0 = (c + 1) * KB;
#pragma unroll
            for (int p = 0; p < 8; p++)
                xr[p] = xbase[(size_t)(lr + 16 * p) * D_MODEL + k0 + lk];
#pragma unroll
            for (int p = 0; p < 4; p++)
                wr[p] = wg[(size_t)(lr + 16 * p) * D_MODEL + k0 + lk];
        }

#pragma unroll
        for (int kk = 0; kk < KB; kk++) {
            const unsigned long long* xp =
                (const unsigned long long*)&sm.g.Xs[b][kk][ty * 8];
            unsigned long long xv0 = xp[0], xv1 = xp[1], xv2 = xp[2], xv3 = xp[3];
            float4 wv = *(const float4*)&sm.g.Ws[b][kk][tx * 4];
            unsigned long long w0 = pack2(wv.x), w1 = pack2(wv.y),
                               w2 = pack2(wv.z), w3 = pack2(wv.w);
            ffma2(acc[0][0], xv0, w0); ffma2(acc[0][1], xv0, w1);
            ffma2(acc[0][2], xv0, w2); ffma2(acc[0][3], xv0, w3);
            ffma2(acc[1][0], xv1, w0); ffma2(acc[1][1], xv1, w1);
            ffma2(acc[1][2], xv1, w2); ffma2(acc[1][3], xv1, w3);
            ffma2(acc[2][0], xv2, w0); ffma2(acc[2][1], xv2, w1);
            ffma2(acc[2][2], xv2, w2); ffma2(acc[2][3], xv2, w3);
            ffma2(acc[3][0], xv3, w0); ffma2(acc[3][1], xv3, w1);
            ffma2(acc[3][2], xv3, w2); ffma2(acc[3][3], xv3, w3);
        }

        if (c + 1 < NC) {
            __syncthreads();   // everyone done reading buf (c-1)&1 == (c+1)&1
            const int nb = b ^ 1;
#pragma unroll
            for (int p = 0; p < 8; p++) sm.g.Xs[nb][lk][lr + 16 * p] = xr[p];
#pragma unroll
            for (int p = 0; p < 4; p++) sm.g.Ws[nb][lk][lr + 16 * p] = wr[p];
            __syncthreads();
        }
    }
    __syncthreads();   // done with gemm smem; safe to overwrite with epilogue union

    // ---- write logits to smem ----
#pragma unroll
    for (int i = 0; i < 4; i++) {
#pragma unroll
        for (int j = 0; j < 4; j++) {
            float2 v;
            unsigned long long u = acc[i][j];
            v.x = __uint_as_float((unsigned)(u & 0xffffffffull));
            v.y = __uint_as_float((unsigned)(u >> 32));
            sm.e.L[ty * 8 + 2 * i + 0][tx * 4 + j] = v.x;
            sm.e.L[ty * 8 + 2 * i + 1][tx * 4 + j] = v.y;
        }
    }
    if (tid < N_EXP) sm.e.hist[tid] = 0;
    __syncthreads();

    // ---- phase A: per-token softmax stats + top-2 + outputs ----
    if (tid < TM) {
        const int t = tid;
        float m1 = -1e30f, m2 = -1e30f;
        int i1 = 0, i2 = 0;
#pragma unroll
        for (int e = 0; e < N_EXP; e++) {
            float v = sm.e.L[t][e];
            if (v > m1)      { m2 = m1; i2 = i1; m1 = v; i1 = e; }
            else if (v > m2) { m2 = v;  i2 = e; }
        }
        float s = 0.0f;
#pragma unroll
        for (int e = 0; e < N_EXP; e++) s += __expf(sm.e.L[t][e] - m1);
        float rcp = 1.0f / s;

        const int gt = tokBase + t;
        out[(size_t)gt * 2 + 0] = (float)i1;
        out[(size_t)gt * 2 + 1] = (float)i2;
        out[(size_t)2 * S_TOKENS + (size_t)gt * 2 + 0] = rcp;                    // exp(0)*rcp
        out[(size_t)2 * S_TOKENS + (size_t)gt * 2 + 1] = __expf(m2 - m1) * rcp;

        sm.e.tmax[t] = m1;
        sm.e.trcp[t] = rcp;
        atomicAdd(&sm.e.hist[i1], 1);
    }
    __syncthreads();

    // ---- phase B: importance partial sums (expert-parallel) ----
    {
        const int e = tid & 63;
        const int g = tid >> 6;       // 4 token groups of 32
        float p = 0.0f;
#pragma unroll
        for (int r = 0; r < 32; r++) {
            int t = g * 32 + r;
            p += __expf(sm.e.L[t][e] - sm.e.tmax[t]) * sm.e.trcp[t];
        }
        atomicAdd(&g_imp[e], p);
        if (tid < N_EXP) atomicAdd(&g_cnt[tid], sm.e.hist[tid]);
    }
}

__global__ void finalize_kernel(float* __restrict__ out) {
    const int e = threadIdx.x;   // 64 threads
    float v = g_imp[e] * (float)g_cnt[e];
#pragma unroll
    for (int o = 16; o > 0; o >>= 1) v += __shfl_down_sync(0xffffffffu, v, o);
    __shared__ float s2[2];
    if ((e & 31) == 0) s2[e >> 5] = v;
    __syncthreads();
    if (e == 0) {
        float tot = s2[0] + s2[1];
        out[(size_t)4 * S_TOKENS] =
            (float)N_EXP * tot / ((float)S_TOKENS * (float)S_TOKENS);
    }
}

extern "C" void kernel_launch(void* const* d_in, const int* in_sizes, int n_in,
                              void* d_out, int out_size)
{
    const float* x  = (const float*)d_in[0];
    const float* wg = (const float*)d_in[1];
    float* out = (float*)d_out;

    zero_kernel<<<1, 64>>>();
    gate_kernel<<<S_TOKENS / TM, 256>>>(x, wg, out);
    finalize_kernel<<<1, 64>>>(out);
}

// round 4
// speedup vs baseline: 1.1039x; 1.1039x over previous
#include <cuda_runtime.h>
#include <cstdint>

#define S_TOKENS 16384
#define D_MODEL  4096
#define N_EXP    64
#define TM       128               // tokens per CTA
#define KC       32                // K per chunk
#define NITER    (D_MODEL / KC)    // 128
#define XSTR     36                // floats per row in smem (conflict-free)
#define X_FLOATS (TM * XSTR)       // 4608
#define W_FLOATS (N_EXP * XSTR)    // 2304
#define STAGE_FLOATS (X_FLOATS + W_FLOATS)   // 6912
#define SMEM_FLOATS  (2 * STAGE_FLOATS)      // 13824 -> 55296 B
#define L_STR    65
#define DELTA    1e-3f

__device__ float g_imp[N_EXP];
__device__ int   g_cnt[N_EXP];

__global__ void zero_kernel() {
    int t = threadIdx.x;
    if (t < N_EXP) { g_imp[t] = 0.0f; g_cnt[t] = 0; }
}

__device__ __forceinline__ void mma_tf32(float* c,
                                         uint32_t a0, uint32_t a1,
                                         uint32_t a2, uint32_t a3,
                                         uint32_t b0, uint32_t b1) {
    asm volatile(
        "mma.sync.aligned.m16n8k8.row.col.f32.tf32.tf32.f32 "
        "{%0,%1,%2,%3}, {%4,%5,%6,%7}, {%8,%9}, {%0,%1,%2,%3};"
        : "+f"(c[0]), "+f"(c[1]), "+f"(c[2]), "+f"(c[3])
        : "r"(a0), "r"(a1), "r"(a2), "r"(a3), "r"(b0), "r"(b1));
}

__device__ __forceinline__ uint32_t hi_mask(float v) {
    return __float_as_uint(v) & 0xFFFFE000u;
}

__global__ __launch_bounds__(256, 1)
void gate_kernel(const float* __restrict__ x,
                 const float* __restrict__ wg,
                 float* __restrict__ out)
{
    extern __shared__ float smem[];
    const int tid     = threadIdx.x;
    const int lane    = tid & 31;
    const int wid     = tid >> 5;          // 0..7
    const int tokBase = blockIdx.x * TM;

    // ---- loader mapping ----
    const int xt = tid >> 1, xh = tid & 1;         // x: row, 16-float half
    const int wr = tid >> 2, wq = tid & 3;         // w: row, 8-float quarter
    const float* xrow = x  + (size_t)(tokBase + xt) * D_MODEL + xh * 16;
    const float* wrow = wg + (size_t)wr * D_MODEL + wq * 8;
    float* xs_dst0 = smem + xt * XSTR + xh * 16;
    float* ws_dst0 = smem + X_FLOATS + wr * XSTR + wq * 8;

    float4 xb[4];
    float4 wb[2];

    // prologue: chunk 0 -> regs -> stage 0
#pragma unroll
    for (int i = 0; i < 4; i++) xb[i] = *(const float4*)(xrow + i * 4);
#pragma unroll
    for (int j = 0; j < 2; j++) wb[j] = *(const float4*)(wrow + j * 4);
#pragma unroll
    for (int i = 0; i < 4; i++) *(float4*)(xs_dst0 + i * 4) = xb[i];
#pragma unroll
    for (int j = 0; j < 2; j++) *(float4*)(ws_dst0 + j * 4) = wb[j];
    __syncthreads();

    // ---- compute mapping ----
    const int r  = lane >> 2;   // 0..7
    const int ci = lane & 3;    // 0..3
    const int m0 = wid * 16;    // warp's token block

    float acc[8][4];
#pragma unroll
    for (int n = 0; n < 8; n++)
#pragma unroll
        for (int q = 0; q < 4; q++) acc[n][q] = 0.0f;

    for (int c = 0; c < NITER; c++) {
        const int b = c & 1;
        const float* Xs = smem + b * STAGE_FLOATS;
        const float* Ws = smem + b * STAGE_FLOATS + X_FLOATS;

        // prefetch next chunk into registers (overlaps with compute below)
        if (c + 1 < NITER) {
            const float* xp = xrow + (c + 1) * KC;
            const float* wp = wrow + (c + 1) * KC;
#pragma unroll
            for (int i = 0; i < 4; i++) xb[i] = *(const float4*)(xp + i * 4);
#pragma unroll
            for (int j = 0; j < 2; j++) wb[j] = *(const float4*)(wp + j * 4);
        }

#pragma unroll
        for (int ks = 0; ks < 4; ks++) {
            const int k0 = ks * 8;
            // A fragment (16x8) raw fp32, then exact tf32 split
            float a0 = Xs[(m0 + r)     * XSTR + k0 + ci];
            float a1 = Xs[(m0 + r + 8) * XSTR + k0 + ci];
            float a2 = Xs[(m0 + r)     * XSTR + k0 + ci + 4];
            float a3 = Xs[(m0 + r + 8) * XSTR + k0 + ci + 4];
            uint32_t ah0 = hi_mask(a0), ah1 = hi_mask(a1),
                     ah2 = hi_mask(a2), ah3 = hi_mask(a3);
            uint32_t al0 = __float_as_uint(a0 - __uint_as_float(ah0));
            uint32_t al1 = __float_as_uint(a1 - __uint_as_float(ah1));
            uint32_t al2 = __float_as_uint(a2 - __uint_as_float(ah2));
            uint32_t al3 = __float_as_uint(a3 - __uint_as_float(ah3));

#pragma unroll
            for (int n = 0; n < 8; n++) {
                // B fragment (8x8 col-major): expert = n*8 + r, k = k0+ci / +4
                float b0 = Ws[(n * 8 + r) * XSTR + k0 + ci];
                float b1 = Ws[(n * 8 + r) * XSTR + k0 + ci + 4];
                uint32_t bh0 = hi_mask(b0), bh1 = hi_mask(b1);
                uint32_t bl0 = __float_as_uint(b0 - __uint_as_float(bh0));
                uint32_t bl1 = __float_as_uint(b1 - __uint_as_float(bh1));

                mma_tf32(acc[n], ah0, ah1, ah2, ah3, bh0, bh1);
                mma_tf32(acc[n], ah0, ah1, ah2, ah3, bl0, bl1);
                mma_tf32(acc[n], al0, al1, al2, al3, bh0, bh1);
            }
        }

        if (c + 1 < NITER) {
            const int nb = b ^ 1;
            float* xd = xs_dst0 + nb * STAGE_FLOATS;
            float* wd = ws_dst0 + nb * STAGE_FLOATS;
#pragma unroll
            for (int i = 0; i < 4; i++) *(float4*)(xd + i * 4) = xb[i];
#pragma unroll
            for (int j = 0; j < 2; j++) *(float4*)(wd + j * 4) = wb[j];
            __syncthreads();
        }
    }
    __syncthreads();   // gemm smem dead; reuse for epilogue

    // ---- epilogue smem layout (overlays gemm stages) ----
    float* Lp    = smem;                        // [128][65] logits
    float* tmax  = smem + TM * L_STR;           // [128]  (8320..)
    float* tm2   = tmax + TM;                   // [128]
    float* trcp  = tm2 + TM;                    // [128]
    int*   hist  = (int*)(trcp + TM);           // [64]
    int*   i1s   = (int*)(hist + N_EXP);        // [128]
    int*   wl    = (int*)(i1s + TM);            // [128]
    int*   nflag = (int*)(wl + TM);             // [1]

    // scatter accumulators to L
#pragma unroll
    for (int n = 0; n < 8; n++) {
        const int col = n * 8 + 2 * ci;
        Lp[(m0 + r)     * L_STR + col]     = acc[n][0];
        Lp[(m0 + r)     * L_STR + col + 1] = acc[n][1];
        Lp[(m0 + r + 8) * L_STR + col]     = acc[n][2];
        Lp[(m0 + r + 8) * L_STR + col + 1] = acc[n][3];
    }
    if (tid < N_EXP) hist[tid] = 0;
    if (tid == 0) nflag[0] = 0;
    __syncthreads();

    // phase A: per-token top-3 + softmax stats + provisional outputs
    if (tid < TM) {
        const int t = tid;
        float m1 = -1e30f, m2v = -1e30f, m3v = -1e30f;
        int i1 = 0, i2 = 0;
#pragma unroll
        for (int e = 0; e < N_EXP; e++) {
            float v = Lp[t * L_STR + e];
            if (v > m1)       { m3v = m2v; m2v = m1; i2 = i1; m1 = v; i1 = e; }
            else if (v > m2v) { m3v = m2v; m2v = v;  i2 = e; }
            else if (v > m3v) { m3v = v; }
        }
        float s = 0.0f;
#pragma unroll
        for (int e = 0; e < N_EXP; e++) s += __expf(Lp[t * L_STR + e] - m1);
        float rcp = 1.0f / s;

        const int gt = tokBase + t;
        out[(size_t)gt * 2 + 0] = (float)i1;
        out[(size_t)gt * 2 + 1] = (float)i2;
        out[(size_t)2 * S_TOKENS + (size_t)gt * 2 + 0] = rcp;
        out[(size_t)2 * S_TOKENS + (size_t)gt * 2 + 1] = __expf(m2v - m1) * rcp;

        tmax[t] = m1;
        tm2[t]  = m2v;
        trcp[t] = rcp;
        i1s[t]  = i1;
        atomicAdd(&hist[i1], 1);

        if ((m1 - m2v) < DELTA || (m2v - m3v) < DELTA) {
            int idx = atomicAdd(nflag, 1);
            wl[idx] = t;
        }
    }
    __syncthreads();

    // near-tie repair: exact fp32 recompute of candidate experts (warp per token)
    {
        const int nf = nflag[0];
        for (int wi = wid; wi < nf; wi += 8) {
            const int t = wl[wi];
            const float thresh = tm2[t] - DELTA;
            const float4* xr4 = (const float4*)(x + (size_t)(tokBase + t) * D_MODEL);
            float e1 = -1e30f, e2 = -1e30f;
            int j1 = 0, j2 = 0;
            for (int e = 0; e < N_EXP; e++) {
                if (Lp[t * L_STR + e] >= thresh) {   // warp-uniform
                    const float4* wr4 = (const float4*)(wg + (size_t)e * D_MODEL);
                    float s = 0.0f;
#pragma unroll 4
                    for (int i = lane; i < D_MODEL / 4; i += 32) {
                        float4 xv = xr4[i];
                        float4 wv = wr4[i];
                        s += xv.x * wv.x; s += xv.y * wv.y;
                        s += xv.z * wv.z; s += xv.w * wv.w;
                    }
#pragma unroll
                    for (int o = 16; o > 0; o >>= 1)
                        s += __shfl_xor_sync(0xffffffffu, s, o);
                    if (s > e1)      { e2 = e1; j2 = j1; e1 = s; j1 = e; }
                    else if (s > e2) { e2 = s;  j2 = e; }
                }
            }
            if (lane == 0) {
                const int gt = tokBase + t;
                out[(size_t)gt * 2 + 0] = (float)j1;
                out[(size_t)gt * 2 + 1] = (float)j2;
                out[(size_t)2 * S_TOKENS + (size_t)gt * 2 + 0] =
                    __expf(e1 - tmax[t]) * trcp[t];
                out[(size_t)2 * S_TOKENS + (size_t)gt * 2 + 1] =
                    __expf(e2 - tmax[t]) * trcp[t];
                if (j1 != i1s[t]) {
                    atomicAdd(&hist[i1s[t]], -1);
                    atomicAdd(&hist[j1], 1);
                }
            }
        }
    }
    __syncthreads();

    // phase B: importance partial sums (expert-parallel) + load counts
    {
        const int e = tid & 63;
        const int g = tid >> 6;
        float p = 0.0f;
#pragma unroll
        for (int rr = 0; rr < 32; rr++) {
            int t = g * 32 + rr;
            p += __expf(Lp[t * L_STR + e] - tmax[t]) * trcp[t];
        }
        atomicAdd(&g_imp[e], p);
        if (tid < N_EXP) atomicAdd(&g_cnt[tid], hist[tid]);
    }
}

__global__ void finalize_kernel(float* __restrict__ out) {
    const int e = threadIdx.x;   // 64 threads
    float v = g_imp[e] * (float)g_cnt[e];
#pragma unroll
    for (int o = 16; o > 0; o >>= 1) v += __shfl_down_sync(0xffffffffu, v, o);
    __shared__ float s2[2];
    if ((e & 31) == 0) s2[e >> 5] = v;
    __syncthreads();
    if (e == 0) {
        float tot = s2[0] + s2[1];
        out[(size_t)4 * S_TOKENS] =
            (float)N_EXP * tot / ((float)S_TOKENS * (float)S_TOKENS);
    }
}

extern "C" void kernel_launch(void* const* d_in, const int* in_sizes, int n_in,
                              void* d_out, int out_size)
{
    const float* x  = (const float*)d_in[0];
    const float* wg = (const float*)d_in[1];
    float* out = (float*)d_out;

    static int configured = 0;
    if (!configured) {
        cudaFuncSetAttribute(gate_kernel,
                             cudaFuncAttributeMaxDynamicSharedMemorySize,
                             SMEM_FLOATS * (int)sizeof(float));
        configured = 1;
    }

    zero_kernel<<<1, 64>>>();
    gate_kernel<<<S_TOKENS / TM, 256, SMEM_FLOATS * sizeof(float)>>>(x, wg, out);
    finalize_kernel<<<1, 64>>>(out);
}